// round 16
// baseline (speedup 1.0000x reference)
#include <cuda_runtime.h>
#include <cuda_fp8.h>
#include <cstdint>
#include <cstddef>

#define K_DIM 1024
#define N_DIM 1024
#define NKB 32
#define LN2F 0.69314718246459960938f

#define BM 128
#define BN 128
#define BK 32                 // bytes per k-block (fp8) == one MX block
#define RSTRIDE 48            // bytes per smem row (32 data + 16 pad)
#define STG_BYTES (BM * RSTRIDE)
#define NSTG 5                // pipeline stages (prefetch distance 4)
#define OFF_A32 (2 * NSTG * STG_BYTES)       // 61440: fp32 A staging (32 rows x 36f)
#define OFF_B32 (OFF_A32 + 32 * 36 * 4)      // 66048: fp32 B staging [k][n] 32x128
#define DYN_TOTAL (OFF_B32 + 32 * 128 * 4)   // 82432

// Exact e5m2 grid values stored AS fp8 + per-32-block scales (fp32, inexact jax)
__device__ __align__(16) uint8_t g_xv[(size_t)8 * 8192 * 1024];
__device__ __align__(16) uint8_t g_wv[(size_t)1024 * 1024];
__device__ __align__(16) float g_xs[(size_t)NKB * 65536];   // [kb][row]
__device__ __align__(16) float g_ws[(size_t)NKB * 1024];    // [kb][row]

// Rare path outlined: keeps libdevice logf out of the hot loops' I$ footprint.
__device__ __noinline__ int slow_floor_log2(float s) {
    return (int)floorf(logf(s) / LN2F);
}
__device__ __forceinline__ int jax_floor_log2(float s) {
    uint32_t b = __float_as_uint(s);
    uint32_t mant = b & 0x7fffffu;
    int ef = (int)(b >> 23);
    if (ef == 0 || mant >= 0x7ff000u || (mant != 0u && mant <= 0x4000u))
        return slow_floor_log2(s);
    return ef - 127;
}
__device__ __forceinline__ float jax_scale(float amax) {
    if (!(amax > 0.f)) return 1.f;
    int E = jax_floor_log2(amax);
    return expf((float)(E - 15) * LN2F);
}

// Markstein correctly-rounded division finish (rb = RN(1/b) hoisted).
__device__ __forceinline__ float div_cr(float a, float b, float rb) {
    float q0 = a * rb;
    float e = fmaf(-b, q0, a);
    return fmaf(e, rb, q0);
}

__device__ __forceinline__ float e5m2_one(float t, const float* sStep,
                                          const float* sRStep) {
    uint32_t tb = __float_as_uint(t);
    float av = __uint_as_float(tb & 0x7fffffffu);
    float r = 0.f;
    if (av > 0.f) {
        float sat = fminf(av, 57344.f);
        int e = jax_floor_log2(sat);
        e = e < -14 ? -14 : e;
        float step = sStep[e + 14];
        float n = rintf(div_cr(sat, step, sRStep[e + 14]));
        float p2 = __uint_as_float((uint32_t)(e + 125) << 23);
        float mag = n * p2;
        r = __uint_as_float(__float_as_uint(mag) | (tb & 0x80000000u));
    }
    return r;
}

__device__ __forceinline__ unsigned short cvt2_e5m2(float hi, float lo) {
    unsigned short r;
    asm("cvt.rn.satfinite.e5m2x2.f32 %0, %1, %2;" : "=h"(r) : "f"(hi), "f"(lo));
    return r;
}

// 4 threads per 32-element MX block (8 elements each); amax via quad shfl.
__global__ __launch_bounds__(256) void quant_v(const float* __restrict__ x,
                                               uint8_t* __restrict__ qv,
                                               float* __restrict__ qs,
                                               int nquart, int rows) {
    __shared__ float sStep[30];
    __shared__ float sRStep[30];
    if (threadIdx.x < 30) {
        float st = expf((float)((int)threadIdx.x - 16) * LN2F);
        sStep[threadIdx.x] = st;
        sRStep[threadIdx.x] = 1.0f / st;
    }
    __syncthreads();
    int q = blockIdx.x * 256 + threadIdx.x;
    if (q >= nquart) return;

    const float4* p = reinterpret_cast<const float4*>(x) + (size_t)q * 2;
    float4 v0 = p[0], v1 = p[1];
    float am = fmaxf(fmaxf(fmaxf(fabsf(v0.x), fabsf(v0.y)),
                           fmaxf(fabsf(v0.z), fabsf(v0.w))),
                     fmaxf(fmaxf(fabsf(v1.x), fabsf(v1.y)),
                           fmaxf(fabsf(v1.z), fabsf(v1.w))));
    am = fmaxf(am, __shfl_xor_sync(0xffffffffu, am, 1));
    am = fmaxf(am, __shfl_xor_sync(0xffffffffu, am, 2));

    float scale = jax_scale(am);
    float rscale = 1.0f / scale;

    float f[8] = {v0.x, v0.y, v0.z, v0.w, v1.x, v1.y, v1.z, v1.w};
    unsigned short o[4];
#pragma unroll
    for (int i = 0; i < 8; i += 2) {
        float t0 = div_cr(f[i], scale, rscale);
        float t1 = div_cr(f[i + 1], scale, rscale);
        float r0 = e5m2_one(t0, sStep, sRStep);
        float r1 = e5m2_one(t1, sStep, sRStep);
        o[i >> 1] = cvt2_e5m2(r1, r0);
    }
    unsigned long long pk;
    asm("mov.b64 %0, {%1, %2};" : "=l"(pk)
        : "r"((uint32_t)o[0] | ((uint32_t)o[1] << 16)),
          "r"((uint32_t)o[2] | ((uint32_t)o[3] << 16)));
    *reinterpret_cast<unsigned long long*>(qv + (size_t)q * 8) = pk;

    if ((q & 3) == 0) {
        int b = q >> 2;
        qs[(size_t)(b & 31) * rows + (b >> 5)] = scale;
    }
}

__device__ __forceinline__ void cp_async16(uint32_t dst, const void* src) {
    asm volatile("cp.async.cg.shared.global [%0], [%1], 16;\n" :: "r"(dst), "l"(src));
}
__device__ __forceinline__ unsigned long long pk2(float lo, float hi) {
    unsigned long long r;
    asm("mov.b64 %0, {%1, %2};" : "=l"(r) : "f"(lo), "f"(hi));
    return r;
}
__device__ __forceinline__ float2 upk2(unsigned long long v) {
    float2 r;
    asm("mov.b64 {%0, %1}, %2;" : "=f"(r.x), "=f"(r.y) : "l"(v));
    return r;
}
__device__ __forceinline__ unsigned long long mul2(unsigned long long a,
                                                   unsigned long long b) {
    unsigned long long r;
    asm("mul.rn.f32x2 %0, %1, %2;" : "=l"(r) : "l"(a), "l"(b));
    return r;
}
__device__ __forceinline__ void fma2(unsigned long long& acc, unsigned long long a,
                                     unsigned long long b) {
    asm("fma.rn.f32x2 %0, %1, %2, %0;" : "+l"(acc) : "l"(a), "l"(b));
}
// Exact e5m2x2 -> two fp32 (low byte -> f0).
__device__ __forceinline__ void e5m2x2_f32(uint32_t u16, float& f0, float& f1) {
    uint32_t h2;
    asm("cvt.rn.f16x2.e5m2x2 %0, %1;" : "=r"(h2) : "h"((unsigned short)u16));
    asm("{ .reg .f16 a,b;\n\t mov.b32 {a,b}, %2;\n\t"
        "cvt.f32.f16 %0, a;\n\t cvt.f32.f16 %1, b; }"
        : "=f"(f0), "=f"(f1) : "r"(h2));
}
__device__ __forceinline__ void cvt8(uint32_t w0, uint32_t w1, float* f) {
    e5m2x2_f32(w0 & 0xffffu, f[0], f[1]);
    e5m2x2_f32(w0 >> 16, f[2], f[3]);
    e5m2x2_f32(w1 & 0xffffu, f[4], f[5]);
    e5m2x2_f32(w1 >> 16, f[6], f[7]);
}

// Dual-pipe 128x128 GEMM: warps 4..15 = tensor (rows 0..95, fp8 m16n8k32 mma),
// warps 0..3 = FFMA2 (rows 96..127) consuming fp32 operands converted in-smem
// from the fp8 tiles. Same per-32-block scale fold; literal jax out-quant.
__global__ __launch_bounds__(512) void gemm_qd(const float* __restrict__ bias,
                                               float* __restrict__ out, int mrows) {
    extern __shared__ uint8_t dynsm[];
    uint8_t* sA = dynsm;
    uint8_t* sB = dynsm + NSTG * STG_BYTES;
    float* sA32f = (float*)(dynsm + OFF_A32);   // [32][36]
    float* sB32f = (float*)(dynsm + OFF_B32);   // [k 32][n 128]
    __shared__ float sSX[NSTG][BM];
    __shared__ float sSW[NSTG][BN];
    __shared__ float sBias[BN];
    __shared__ float sStep[30];
    __shared__ float sRStep[30];

    const int tid = threadIdx.x;
    const int m0 = blockIdx.y * BM;
    const int n0 = blockIdx.x * BN;
    if (tid < 30) {
        float st = expf((float)(tid - 16) * LN2F);
        sStep[tid] = st;
        sRStep[tid] = 1.0f / st;
    }
    if (tid < BN) sBias[tid] = bias[n0 + tid];

    const int lane = tid & 31;
    const int warp = tid >> 5;          // 0..15 (0..3 FFMA, 4..15 tensor)
    const int tw = warp - 4;
    const int wm = tw >> 2;             // 0..2
    const int wn = tw & 3;              // 0..3

    uint32_t sAu[NSTG], sBu[NSTG], sSXu[NSTG], sSWu[NSTG];
#pragma unroll
    for (int s = 0; s < NSTG; s++) {
        sAu[s] = (uint32_t)__cvta_generic_to_shared(sA + s * STG_BYTES);
        sBu[s] = (uint32_t)__cvta_generic_to_shared(sB + s * STG_BYTES);
        sSXu[s] = (uint32_t)__cvta_generic_to_shared(&sSX[s][0]);
        sSWu[s] = (uint32_t)__cvta_generic_to_shared(&sSW[s][0]);
    }

    unsigned long long accU[16];
#pragma unroll
    for (int i = 0; i < 16; i++) accU[i] = 0ull;

    const int lrow = (tid & 255) >> 1, lch = tid & 1;
    auto load_stage = [&](int stage, int kt) {
        int k0 = kt * BK;
        if (tid < 256)
            cp_async16(sAu[stage] + (uint32_t)(lrow * RSTRIDE + lch * 16),
                       &g_xv[(size_t)(m0 + lrow) * K_DIM + k0 + lch * 16]);
        else
            cp_async16(sBu[stage] + (uint32_t)(lrow * RSTRIDE + lch * 16),
                       &g_wv[(size_t)(n0 + lrow) * K_DIM + k0 + lch * 16]);
        if (tid < 32)
            cp_async16(sSXu[stage] + tid * 16, &g_xs[(size_t)kt * mrows + m0 + tid * 4]);
        else if (tid < 64)
            cp_async16(sSWu[stage] + (tid - 32) * 16,
                       &g_ws[(size_t)kt * N_DIM + n0 + (tid - 32) * 4]);
        asm volatile("cp.async.commit_group;\n");
    };

    const int gid = lane >> 2, tig = lane & 3;
    const int mg = lane >> 2, ng = lane & 3;   // FFMA lane mapping
    const int NK = K_DIM / BK;   // 32

#pragma unroll
    for (int s = 0; s < 4; s++) load_stage(s, s);

    int st = 0;
    for (int kt = 0; kt < NK; kt++) {
        if (kt < NK - 3)       asm volatile("cp.async.wait_group 3;\n");
        else if (kt == NK - 3) asm volatile("cp.async.wait_group 2;\n");
        else if (kt == NK - 2) asm volatile("cp.async.wait_group 1;\n");
        else                   asm volatile("cp.async.wait_group 0;\n");
        __syncthreads();

        if (kt + 4 < NK) {
            int pf = st + 4 >= NSTG ? st - 1 : st + 4;
            load_stage(pf, kt + 4);
        }

        if (warp >= 4) {
            // ---------------- tensor path (rows 0..95) ----------------
            unsigned long long sxp[2][2], swp[4];
#pragma unroll
            for (int mf = 0; mf < 2; mf++) {
                float s0 = sSX[st][wm * 32 + mf * 16 + gid];
                float s1 = sSX[st][wm * 32 + mf * 16 + 8 + gid];
                sxp[mf][0] = pk2(s0, s0);
                sxp[mf][1] = pk2(s1, s1);
            }
#pragma unroll
            for (int nf = 0; nf < 4; nf++)
                swp[nf] = pk2(sSW[st][wn * 32 + nf * 8 + tig * 2],
                              sSW[st][wn * 32 + nf * 8 + tig * 2 + 1]);

            uint32_t a[2][4];
#pragma unroll
            for (int mf = 0; mf < 2; mf++) {
                uint32_t addr = sAu[st] +
                    (uint32_t)((wm * 32 + mf * 16 + (lane & 15)) * RSTRIDE +
                               (lane >> 4) * 16);
                asm volatile("ldmatrix.sync.aligned.m8n8.x4.shared.b16 {%0,%1,%2,%3}, [%4];\n"
                             : "=r"(a[mf][0]), "=r"(a[mf][1]), "=r"(a[mf][2]), "=r"(a[mf][3])
                             : "r"(addr));
            }
            uint32_t b[4][2];
#pragma unroll
            for (int np = 0; np < 2; np++) {
                uint32_t addr = sBu[st] +
                    (uint32_t)((wn * 32 + np * 16 + ((lane >> 4) & 1) * 8 + (lane & 7)) * RSTRIDE +
                               ((lane >> 3) & 1) * 16);
                asm volatile("ldmatrix.sync.aligned.m8n8.x4.shared.b16 {%0,%1,%2,%3}, [%4];\n"
                             : "=r"(b[np * 2][0]), "=r"(b[np * 2][1]),
                               "=r"(b[np * 2 + 1][0]), "=r"(b[np * 2 + 1][1])
                             : "r"(addr));
            }
#pragma unroll
            for (int mf = 0; mf < 2; mf++)
#pragma unroll
                for (int nf = 0; nf < 4; nf++) {
                    float c0 = 0.f, c1 = 0.f, c2 = 0.f, c3 = 0.f;
                    asm volatile(
                        "mma.sync.aligned.m16n8k32.row.col.f32.e5m2.e5m2.f32 "
                        "{%0,%1,%2,%3}, {%4,%5,%6,%7}, {%8,%9}, {%0,%1,%2,%3};\n"
                        : "+f"(c0), "+f"(c1), "+f"(c2), "+f"(c3)
                        : "r"(a[mf][0]), "r"(a[mf][1]), "r"(a[mf][2]), "r"(a[mf][3]),
                          "r"(b[nf][0]), "r"(b[nf][1]));
                    fma2(accU[mf * 8 + nf * 2 + 0], pk2(c0, c1), mul2(sxp[mf][0], swp[nf]));
                    fma2(accU[mf * 8 + nf * 2 + 1], pk2(c2, c3), mul2(sxp[mf][1], swp[nf]));
                }
        } else {
            // ------------- FFMA path (rows 96..127), convert + compute -------------
            // Convert A rows 96..127 (this thread: 1 row-octet) from fp8.
            {
                int row = 96 + (tid >> 2), oct = tid & 3;
                uint32_t src = sAu[st] + (uint32_t)(row * RSTRIDE + oct * 8);
                uint32_t w0, w1;
                asm volatile("ld.shared.v2.u32 {%0,%1}, [%2];" : "=r"(w0), "=r"(w1) : "r"(src));
                float f[8];
                cvt8(w0, w1, f);
                float* d = sA32f + (row - 96) * 36 + oct * 8;
                *reinterpret_cast<float4*>(d) = make_float4(f[0], f[1], f[2], f[3]);
                *reinterpret_cast<float4*>(d + 4) = make_float4(f[4], f[5], f[6], f[7]);
            }
            // Convert B [n][k] fp8 -> [k][n] fp32 (this thread: one n column).
            {
                int n = tid;   // 0..127
#pragma unroll
                for (int pass = 0; pass < 4; pass++) {
                    uint32_t src = sBu[st] + (uint32_t)(n * RSTRIDE + pass * 8);
                    uint32_t w0, w1;
                    asm volatile("ld.shared.v2.u32 {%0,%1}, [%2];" : "=r"(w0), "=r"(w1) : "r"(src));
                    float f[8];
                    cvt8(w0, w1, f);
#pragma unroll
                    for (int kk = 0; kk < 8; kk++)
                        sB32f[(pass * 8 + kk) * 128 + n] = f[kk];
                }
            }
            asm volatile("bar.sync 1, 128;" ::: "memory");

            const int nc0 = warp * 32;
            unsigned long long c2[4][4];
#pragma unroll
            for (int kc = 0; kc < 8; kc++) {
                float4 a4[4];
#pragma unroll
                for (int j = 0; j < 4; j++)
                    a4[j] = *reinterpret_cast<const float4*>(
                        sA32f + (mg * 4 + j) * 36 + kc * 4);
#pragma unroll
                for (int h = 0; h < 4; h++) {
                    const ulonglong2* bp = reinterpret_cast<const ulonglong2*>(
                        sB32f + (kc * 4 + h) * 128 + nc0 + ng * 8);
                    ulonglong2 B0 = bp[0], B1 = bp[1];
#pragma unroll
                    for (int j = 0; j < 4; j++) {
                        float av = (h == 0) ? a4[j].x : (h == 1) ? a4[j].y
                                 : (h == 2) ? a4[j].z : a4[j].w;
                        unsigned long long ap = pk2(av, av);
                        if (kc == 0 && h == 0) {
                            c2[j][0] = mul2(ap, B0.x); c2[j][1] = mul2(ap, B0.y);
                            c2[j][2] = mul2(ap, B1.x); c2[j][3] = mul2(ap, B1.y);
                        } else {
                            fma2(c2[j][0], ap, B0.x); fma2(c2[j][1], ap, B0.y);
                            fma2(c2[j][2], ap, B1.x); fma2(c2[j][3], ap, B1.y);
                        }
                    }
                }
            }
#pragma unroll
            for (int j = 0; j < 4; j++) {
                float sx = sSX[st][96 + mg * 4 + j];
                unsigned long long sx2 = pk2(sx, sx);
#pragma unroll
                for (int p = 0; p < 4; p++) {
                    unsigned long long sw2 = pk2(sSW[st][nc0 + ng * 8 + 2 * p],
                                                 sSW[st][nc0 + ng * 8 + 2 * p + 1]);
                    fma2(accU[j * 4 + p], c2[j][p], mul2(sx2, sw2));
                }
            }
        }

        st = st + 1 >= NSTG ? 0 : st + 1;
    }

    // ---------------- epilogue: literal jax MX e5m2 quant-dequant ----------
    if (warp >= 4) {
#pragma unroll
        for (int mf = 0; mf < 2; mf++) {
#pragma unroll
            for (int h = 0; h < 2; h++) {
                int rl = wm * 32 + mf * 16 + h * 8 + gid;
                float v[8];
                float amax = 0.f;
#pragma unroll
                for (int nf = 0; nf < 4; nf++) {
                    float2 p = upk2(accU[mf * 8 + nf * 2 + h]);
                    float v0 = p.x + sBias[wn * 32 + nf * 8 + tig * 2];
                    float v1 = p.y + sBias[wn * 32 + nf * 8 + tig * 2 + 1];
                    v[nf * 2 + 0] = v0;
                    v[nf * 2 + 1] = v1;
                    amax = fmaxf(amax, fmaxf(fabsf(v0), fabsf(v1)));
                }
                amax = fmaxf(amax, __shfl_xor_sync(0xffffffffu, amax, 1));
                amax = fmaxf(amax, __shfl_xor_sync(0xffffffffu, amax, 2));
                float scale = jax_scale(amax);
                float rscale = 1.0f / scale;
                float* orow = out + (size_t)(m0 + rl) * N_DIM + n0 + wn * 32;
#pragma unroll
                for (int nf = 0; nf < 4; nf++) {
                    float2 qv;
#pragma unroll
                    for (int j = 0; j < 2; j++) {
                        float t = div_cr(v[nf * 2 + j], scale, rscale);
                        float r = e5m2_one(t, sStep, sRStep);
                        (j == 0 ? qv.x : qv.y) = r * scale;
                    }
                    *reinterpret_cast<float2*>(orow + nf * 8 + tig * 2) = qv;
                }
            }
        }
    } else {
        const int nc0 = warp * 32;
#pragma unroll
        for (int j = 0; j < 4; j++) {
            float v[8];
            float amax = 0.f;
#pragma unroll
            for (int p = 0; p < 4; p++) {
                float2 q = upk2(accU[j * 4 + p]);
                float v0 = q.x + sBias[nc0 + ng * 8 + 2 * p];
                float v1 = q.y + sBias[nc0 + ng * 8 + 2 * p + 1];
                v[2 * p] = v0;
                v[2 * p + 1] = v1;
                amax = fmaxf(amax, fmaxf(fabsf(v0), fabsf(v1)));
            }
            amax = fmaxf(amax, __shfl_xor_sync(0xffffffffu, amax, 1));
            amax = fmaxf(amax, __shfl_xor_sync(0xffffffffu, amax, 2));
            float scale = jax_scale(amax);
            float rscale = 1.0f / scale;
            float o[8];
#pragma unroll
            for (int c = 0; c < 8; c++) {
                float t = div_cr(v[c], scale, rscale);
                float r = e5m2_one(t, sStep, sRStep);
                o[c] = r * scale;
            }
            float* orow = out + (size_t)(m0 + 96 + mg * 4 + j) * N_DIM + n0 + nc0 + ng * 8;
            *reinterpret_cast<float4*>(orow) = make_float4(o[0], o[1], o[2], o[3]);
            *reinterpret_cast<float4*>(orow + 4) = make_float4(o[4], o[5], o[6], o[7]);
        }
    }
}

extern "C" void kernel_launch(void* const* d_in, const int* in_sizes, int n_in,
                              void* d_out, int out_size) {
    const float* x = (const float*)d_in[0];
    const float* w = (const float*)d_in[1];
    const float* bias = (const float*)d_in[2];
    float* out = (float*)d_out;

    int Mtot = in_sizes[0] / K_DIM;   // 65536
    int nqx = in_sizes[0] / 8;
    int nqw = in_sizes[1] / 8;

    void *pxv = nullptr, *pwv = nullptr, *pxs = nullptr, *pws = nullptr;
    cudaGetSymbolAddress(&pxv, g_xv);
    cudaGetSymbolAddress(&pwv, g_wv);
    cudaGetSymbolAddress(&pxs, g_xs);
    cudaGetSymbolAddress(&pws, g_ws);

    quant_v<<<(nqx + 255) / 256, 256>>>(x, (uint8_t*)pxv, (float*)pxs, nqx, Mtot);
    quant_v<<<(nqw + 255) / 256, 256>>>(w, (uint8_t*)pwv, (float*)pws, nqw, N_DIM);

    cudaFuncSetAttribute(gemm_qd, cudaFuncAttributeMaxDynamicSharedMemorySize, DYN_TOTAL);
    dim3 grid(N_DIM / BN, Mtot / BM);
    gemm_qd<<<grid, 512, DYN_TOTAL>>>(bias, out, Mtot);
}

// round 17
// speedup vs baseline: 1.7186x; 1.7186x over previous
#include <cuda_runtime.h>
#include <cuda_fp8.h>
#include <cstdint>
#include <cstddef>

#define K_DIM 1024
#define N_DIM 1024
#define NKB 32
#define LN2F 0.69314718246459960938f

#define BM 128
#define BN 128
#define BK 32                 // bytes per k-block (fp8) == one MX block
#define RSTRIDE 48            // bytes per smem row (32 data + 16 pad)
#define STG_BYTES (BM * RSTRIDE)
#define NSTG 5                // pipeline stages (prefetch distance 4)

// Exact e5m2 grid values stored AS fp8 + per-32-block scales (fp32, inexact jax)
__device__ __align__(16) uint8_t g_xv[(size_t)8 * 8192 * 1024];
__device__ __align__(16) uint8_t g_wv[(size_t)1024 * 1024];
__device__ __align__(16) float g_xs[(size_t)NKB * 65536];   // [kb][row]
__device__ __align__(16) float g_ws[(size_t)NKB * 1024];    // [kb][row]

// Rare path outlined: keeps libdevice logf out of the hot loops' I$ footprint.
__device__ __noinline__ int slow_floor_log2(float s) {
    return (int)floorf(logf(s) / LN2F);
}
// floor(logf(s)/ln2f) with exponent-bits fast path (bitwise-equal in fast region)
__device__ __forceinline__ int jax_floor_log2(float s) {
    uint32_t b = __float_as_uint(s);
    uint32_t mant = b & 0x7fffffu;
    int ef = (int)(b >> 23);
    if (ef == 0 || mant >= 0x7ff000u || (mant != 0u && mant <= 0x4000u))
        return slow_floor_log2(s);
    return ef - 127;
}
// Literal jax block scale: expf((floor(log2(amax)) - 15) * ln2f)
__device__ __forceinline__ float jax_scale(float amax) {
    if (!(amax > 0.f)) return 1.f;
    int E = jax_floor_log2(amax);
    return expf((float)(E - 15) * LN2F);
}

// Markstein correctly-rounded division finish: rb = RN(1/b) hoisted.
// Returns RN(a/b) exactly (normal operands, RN mode, fma available).
__device__ __forceinline__ float div_cr(float a, float b, float rb) {
    float q0 = a * rb;
    float e = fmaf(-b, q0, a);
    return fmaf(e, rb, q0);
}

// Literal-jax e5m2 quant of one element (value t already = RN(f/scale) given).
__device__ __forceinline__ float e5m2_one(float t, const float* sStep,
                                          const float* sRStep) {
    uint32_t tb = __float_as_uint(t);
    float av = __uint_as_float(tb & 0x7fffffffu);
    float r = 0.f;
    if (av > 0.f) {
        float sat = fminf(av, 57344.f);
        int e = jax_floor_log2(sat);
        e = e < -14 ? -14 : e;
        float step = sStep[e + 14];
        float n = rintf(div_cr(sat, step, sRStep[e + 14]));  // == rintf(sat/step)
        // ldexpf(n, e-2) == n * 2^(e-2) exactly (n has <=4-bit mantissa)
        float p2 = __uint_as_float((uint32_t)(e + 125) << 23);
        float mag = n * p2;
        r = __uint_as_float(__float_as_uint(mag) | (tb & 0x80000000u));
    }
    return r;
}

__device__ __forceinline__ unsigned short cvt2_e5m2(float hi, float lo) {
    unsigned short r;
    asm("cvt.rn.satfinite.e5m2x2.f32 %0, %1, %2;" : "=h"(r) : "f"(hi), "f"(lo));
    return r;
}

// Fused quant for x AND w: 4 threads per 32-element MX block (8 elements each);
// amax via quad shfl (exactly order-independent). Blocks < nqx/256 handle x;
// the rest handle w. nqx is a multiple of 256*4 so quads never straddle x/w.
__global__ __launch_bounds__(256) void quant_all(const float* __restrict__ x,
                                                 const float* __restrict__ w,
                                                 uint8_t* __restrict__ qvx,
                                                 uint8_t* __restrict__ qvw,
                                                 float* __restrict__ qsx,
                                                 float* __restrict__ qsw,
                                                 int nqx, int nqtot, int mrows) {
    __shared__ float sStep[30];
    __shared__ float sRStep[30];
    if (threadIdx.x < 30) {
        float st = expf((float)((int)threadIdx.x - 16) * LN2F);
        sStep[threadIdx.x] = st;
        sRStep[threadIdx.x] = 1.0f / st;    // exact RN reciprocal
    }
    __syncthreads();
    int q = blockIdx.x * 256 + threadIdx.x;   // global quarter-block id
    if (q >= nqtot) return;

    const bool isw = q >= nqx;
    const int qq = isw ? q - nqx : q;          // local quarter id
    const float* src = isw ? w : x;
    uint8_t* qv = isw ? qvw : qvx;
    float* qs = isw ? qsw : qsx;
    const int rows = isw ? N_DIM : mrows;

    const float4* p = reinterpret_cast<const float4*>(src) + (size_t)qq * 2;
    float4 v0 = p[0], v1 = p[1];
    float am = fmaxf(fmaxf(fmaxf(fabsf(v0.x), fabsf(v0.y)),
                           fmaxf(fabsf(v0.z), fabsf(v0.w))),
                     fmaxf(fmaxf(fabsf(v1.x), fabsf(v1.y)),
                           fmaxf(fabsf(v1.z), fabsf(v1.w))));
    am = fmaxf(am, __shfl_xor_sync(0xffffffffu, am, 1));
    am = fmaxf(am, __shfl_xor_sync(0xffffffffu, am, 2));

    float scale = jax_scale(am);
    float rscale = 1.0f / scale;            // exact RN, hoisted for Markstein

    float f[8] = {v0.x, v0.y, v0.z, v0.w, v1.x, v1.y, v1.z, v1.w};
    unsigned short o[4];
#pragma unroll
    for (int i = 0; i < 8; i += 2) {
        float t0 = div_cr(f[i], scale, rscale);       // == RN(f/scale)
        float t1 = div_cr(f[i + 1], scale, rscale);
        float r0 = e5m2_one(t0, sStep, sRStep);
        float r1 = e5m2_one(t1, sStep, sRStep);
        o[i >> 1] = cvt2_e5m2(r1, r0);      // first src -> high byte
    }
    unsigned long long pk;
    asm("mov.b64 %0, {%1, %2};" : "=l"(pk)
        : "r"((uint32_t)o[0] | ((uint32_t)o[1] << 16)),
          "r"((uint32_t)o[2] | ((uint32_t)o[3] << 16)));
    *reinterpret_cast<unsigned long long*>(qv + (size_t)qq * 8) = pk;

    if ((qq & 3) == 0) {
        int b = qq >> 2;
        qs[(size_t)(b & 31) * rows + (b >> 5)] = scale;
    }
}

__device__ __forceinline__ void cp_async16(uint32_t dst, const void* src) {
    asm volatile("cp.async.cg.shared.global [%0], [%1], 16;\n" :: "r"(dst), "l"(src));
}
__device__ __forceinline__ unsigned long long pk2(float lo, float hi) {
    unsigned long long r;
    asm("mov.b64 %0, {%1, %2};" : "=l"(r) : "f"(lo), "f"(hi));
    return r;
}
__device__ __forceinline__ float2 upk2(unsigned long long v) {
    float2 r;
    asm("mov.b64 {%0, %1}, %2;" : "=f"(r.x), "=f"(r.y) : "l"(v));
    return r;
}
__device__ __forceinline__ unsigned long long mul2(unsigned long long a,
                                                   unsigned long long b) {
    unsigned long long r;
    asm("mul.rn.f32x2 %0, %1, %2;" : "=l"(r) : "l"(a), "l"(b));
    return r;
}
__device__ __forceinline__ void fma2(unsigned long long& acc, unsigned long long a,
                                     unsigned long long b) {
    asm("fma.rn.f32x2 %0, %1, %2, %0;" : "+l"(acc) : "l"(a), "l"(b));
}

// 128x128 tile GEMM, 16 warps (warp tile 32x32), 5-stage cp.async pipeline,
// fp8-e5m2 m16n8k32 MMA (one per MX block) with immediate packed-f32x2 scale
// fold; literal jax out-quant (Markstein CR division) in epilogue.
// (Mainloop measured within 4% of the fallback-HMMA MAC-rate floor; unchanged.)
__global__ __launch_bounds__(512) void gemm_qd(const float* __restrict__ bias,
                                               float* __restrict__ out, int mrows) {
    extern __shared__ uint8_t dynsm[];
    uint8_t* sA = dynsm;                       // [NSTG][STG_BYTES]
    uint8_t* sB = dynsm + NSTG * STG_BYTES;    // [NSTG][STG_BYTES]
    __shared__ float sSX[NSTG][BM];
    __shared__ float sSW[NSTG][BN];
    __shared__ float sBias[BN];
    __shared__ float sStep[30];
    __shared__ float sRStep[30];

    const int tid = threadIdx.x;
    const int m0 = blockIdx.y * BM;
    const int n0 = blockIdx.x * BN;
    if (tid < 30) {
        float st = expf((float)(tid - 16) * LN2F);
        sStep[tid] = st;
        sRStep[tid] = 1.0f / st;
    }
    if (tid < BN) sBias[tid] = bias[n0 + tid];

    const int lane = tid & 31;
    const int warp = tid >> 5;          // 0..15
    const int wm = warp >> 2;           // 0..3  (32 rows)
    const int wn = warp & 3;            // 0..3  (32 cols = one quant block)

    uint32_t sAu[NSTG], sBu[NSTG], sSXu[NSTG], sSWu[NSTG];
#pragma unroll
    for (int s = 0; s < NSTG; s++) {
        sAu[s] = (uint32_t)__cvta_generic_to_shared(sA + s * STG_BYTES);
        sBu[s] = (uint32_t)__cvta_generic_to_shared(sB + s * STG_BYTES);
        sSXu[s] = (uint32_t)__cvta_generic_to_shared(&sSX[s][0]);
        sSWu[s] = (uint32_t)__cvta_generic_to_shared(&sSW[s][0]);
    }

    unsigned long long acc2[2][4][2];
#pragma unroll
    for (int i = 0; i < 2; i++)
#pragma unroll
        for (int j = 0; j < 4; j++)
#pragma unroll
            for (int h = 0; h < 2; h++) acc2[i][j][h] = 0ull;

    // 512 threads: tid<256 loads one 16B chunk of A, tid>=256 one of B.
    const int lrow = (tid & 255) >> 1, lch = tid & 1;
    auto load_stage = [&](int stage, int kt) {
        int k0 = kt * BK;
        if (tid < 256)
            cp_async16(sAu[stage] + (uint32_t)(lrow * RSTRIDE + lch * 16),
                       &g_xv[(size_t)(m0 + lrow) * K_DIM + k0 + lch * 16]);
        else
            cp_async16(sBu[stage] + (uint32_t)(lrow * RSTRIDE + lch * 16),
                       &g_wv[(size_t)(n0 + lrow) * K_DIM + k0 + lch * 16]);
        if (tid < 32)
            cp_async16(sSXu[stage] + tid * 16, &g_xs[(size_t)kt * mrows + m0 + tid * 4]);
        else if (tid < 64)
            cp_async16(sSWu[stage] + (tid - 32) * 16,
                       &g_ws[(size_t)kt * N_DIM + n0 + (tid - 32) * 4]);
        asm volatile("cp.async.commit_group;\n");
    };

    const int gid = lane >> 2, tig = lane & 3;
    const int NK = K_DIM / BK;   // 32

#pragma unroll
    for (int s = 0; s < 4; s++) load_stage(s, s);   // prefetch distance 4

    int st = 0;
    for (int kt = 0; kt < NK; kt++) {
        if (kt < NK - 3)       asm volatile("cp.async.wait_group 3;\n");
        else if (kt == NK - 3) asm volatile("cp.async.wait_group 2;\n");
        else if (kt == NK - 2) asm volatile("cp.async.wait_group 1;\n");
        else                   asm volatile("cp.async.wait_group 0;\n");
        __syncthreads();

        if (kt + 4 < NK) {
            int pf = st + 4 >= NSTG ? st - 1 : st + 4;
            load_stage(pf, kt + 4);
        }

        unsigned long long sxp[2][2], swp[4];
#pragma unroll
        for (int mf = 0; mf < 2; mf++) {
            float s0 = sSX[st][wm * 32 + mf * 16 + gid];
            float s1 = sSX[st][wm * 32 + mf * 16 + 8 + gid];
            sxp[mf][0] = pk2(s0, s0);
            sxp[mf][1] = pk2(s1, s1);
        }
#pragma unroll
        for (int nf = 0; nf < 4; nf++)
            swp[nf] = pk2(sSW[st][wn * 32 + nf * 8 + tig * 2],
                          sSW[st][wn * 32 + nf * 8 + tig * 2 + 1]);

        uint32_t a[2][4];
#pragma unroll
        for (int mf = 0; mf < 2; mf++) {
            uint32_t addr = sAu[st] +
                (uint32_t)((wm * 32 + mf * 16 + (lane & 15)) * RSTRIDE +
                           (lane >> 4) * 16);
            asm volatile("ldmatrix.sync.aligned.m8n8.x4.shared.b16 {%0,%1,%2,%3}, [%4];\n"
                         : "=r"(a[mf][0]), "=r"(a[mf][1]), "=r"(a[mf][2]), "=r"(a[mf][3])
                         : "r"(addr));
        }
        uint32_t b[4][2];
#pragma unroll
        for (int np = 0; np < 2; np++) {
            uint32_t addr = sBu[st] +
                (uint32_t)((wn * 32 + np * 16 + ((lane >> 4) & 1) * 8 + (lane & 7)) * RSTRIDE +
                           ((lane >> 3) & 1) * 16);
            asm volatile("ldmatrix.sync.aligned.m8n8.x4.shared.b16 {%0,%1,%2,%3}, [%4];\n"
                         : "=r"(b[np * 2][0]), "=r"(b[np * 2][1]),
                           "=r"(b[np * 2 + 1][0]), "=r"(b[np * 2 + 1][1])
                         : "r"(addr));
        }

#pragma unroll
        for (int mf = 0; mf < 2; mf++)
#pragma unroll
            for (int nf = 0; nf < 4; nf++) {
                float c0 = 0.f, c1 = 0.f, c2 = 0.f, c3 = 0.f;
                asm volatile(
                    "mma.sync.aligned.m16n8k32.row.col.f32.e5m2.e5m2.f32 "
                    "{%0,%1,%2,%3}, {%4,%5,%6,%7}, {%8,%9}, {%0,%1,%2,%3};\n"
                    : "+f"(c0), "+f"(c1), "+f"(c2), "+f"(c3)
                    : "r"(a[mf][0]), "r"(a[mf][1]), "r"(a[mf][2]), "r"(a[mf][3]),
                      "r"(b[nf][0]), "r"(b[nf][1]));
                fma2(acc2[mf][nf][0], pk2(c0, c1), mul2(sxp[mf][0], swp[nf]));
                fma2(acc2[mf][nf][1], pk2(c2, c3), mul2(sxp[mf][1], swp[nf]));
            }

        st = st + 1 >= NSTG ? 0 : st + 1;
    }

    // Epilogue: +bias, literal jax MX e5m2 quant-dequant over 32 consecutive n.
#pragma unroll
    for (int mf = 0; mf < 2; mf++) {
#pragma unroll
        for (int h = 0; h < 2; h++) {
            int rl = wm * 32 + mf * 16 + h * 8 + gid;
            float v[8];
            float amax = 0.f;
#pragma unroll
            for (int nf = 0; nf < 4; nf++) {
                float2 p = upk2(acc2[mf][nf][h]);
                float v0 = p.x + sBias[wn * 32 + nf * 8 + tig * 2];
                float v1 = p.y + sBias[wn * 32 + nf * 8 + tig * 2 + 1];
                v[nf * 2 + 0] = v0;
                v[nf * 2 + 1] = v1;
                amax = fmaxf(amax, fmaxf(fabsf(v0), fabsf(v1)));
            }
            amax = fmaxf(amax, __shfl_xor_sync(0xffffffffu, amax, 1));
            amax = fmaxf(amax, __shfl_xor_sync(0xffffffffu, amax, 2));
            float scale = jax_scale(amax);
            float rscale = 1.0f / scale;    // exact RN, hoisted for Markstein
            float* orow = out + (size_t)(m0 + rl) * N_DIM + n0 + wn * 32;
#pragma unroll
            for (int nf = 0; nf < 4; nf++) {
                float2 qv;
#pragma unroll
                for (int j = 0; j < 2; j++) {
                    float t = div_cr(v[nf * 2 + j], scale, rscale);  // RN(v/scale)
                    float r = e5m2_one(t, sStep, sRStep);
                    (j == 0 ? qv.x : qv.y) = r * scale;
                }
                *reinterpret_cast<float2*>(orow + nf * 8 + tig * 2) = qv;
            }
        }
    }
}

extern "C" void kernel_launch(void* const* d_in, const int* in_sizes, int n_in,
                              void* d_out, int out_size) {
    const float* x = (const float*)d_in[0];
    const float* w = (const float*)d_in[1];
    const float* bias = (const float*)d_in[2];
    float* out = (float*)d_out;

    int Mtot = in_sizes[0] / K_DIM;   // 65536
    int nqx = in_sizes[0] / 8;        // x quarter-blocks (multiple of 1024)
    int nqw = in_sizes[1] / 8;        // w quarter-blocks
    int nqtot = nqx + nqw;

    void *pxv = nullptr, *pwv = nullptr, *pxs = nullptr, *pws = nullptr;
    cudaGetSymbolAddress(&pxv, g_xv);
    cudaGetSymbolAddress(&pwv, g_wv);
    cudaGetSymbolAddress(&pxs, g_xs);
    cudaGetSymbolAddress(&pws, g_ws);

    quant_all<<<(nqtot + 255) / 256, 256>>>(x, w, (uint8_t*)pxv, (uint8_t*)pwv,
                                            (float*)pxs, (float*)pws,
                                            nqx, nqtot, Mtot);

    const int dyn_smem = NSTG * STG_BYTES * 2;   // 61440 bytes
    cudaFuncSetAttribute(gemm_qd, cudaFuncAttributeMaxDynamicSharedMemorySize, dyn_smem);
    dim3 grid(N_DIM / BN, Mtot / BM);
    gemm_qd<<<grid, 512, dyn_smem>>>(bias, out, Mtot);
}